// round 16
// baseline (speedup 1.0000x reference)
#include <cuda_runtime.h>
#include <cuda_bf16.h>
#include <math.h>
#include <stdint.h>

typedef unsigned long long ull;

// Problem constants
static constexpr int B = 64;
static constexpr int T = 512;
static constexpr int I = 1024;
static constexpr int H = 1024;
static constexpr int G4H = 4 * H;   // 4096

static constexpr int NCTA = 128;

// Scratch in device globals (no allocation allowed)
__device__ float g_xproj[(size_t)T * B * G4H];  // [T][B][4H]
__device__ __nv_bfloat16 g_hbf[2][2][B][H];     // [pingpong][hi/lo][row][k]

// dataflow sync state (monotonic within a launch; re-zeroed by init_kernel)
__device__ unsigned g_wcnt[8 * 32];             // chunk-group write counters, 128B apart
__device__ unsigned g_rdone;                    // read-done counter

// bf16 hi/lo operands for the tensor-core xproj GEMM
__device__ __nv_bfloat16 g_xb_hi[(size_t)B * T * I];   // [m][k]
__device__ __nv_bfloat16 g_xb_lo[(size_t)B * T * I];
__device__ __nv_bfloat16 g_wb_hi[(size_t)G4H * I];     // [fused n][k]  (W^T)
__device__ __nv_bfloat16 g_wb_lo[(size_t)G4H * I];

// ---------------------------------------------------------------------------
// helpers
// ---------------------------------------------------------------------------
__device__ __forceinline__ float fast_tanh(float x) {
    float y; asm("tanh.approx.f32 %0, %1;" : "=f"(y) : "f"(x)); return y;
}
__device__ __forceinline__ float fast_sigmoid(float x) {
    return 0.5f * fast_tanh(0.5f * x) + 0.5f;
}
__device__ __forceinline__ void poll_ge(const unsigned* p, unsigned val) {
    unsigned v;
    do {
        asm volatile("ld.acquire.gpu.global.u32 %0, [%1];"
                     : "=r"(v) : "l"(p) : "memory");
        if (v < val) __nanosleep(32);
    } while (v < val);
}

// mma.sync m16n8k16 bf16 (baseline PTX — compiles for compute_103)
__device__ __forceinline__ void mma_bf16(float* d, const uint32_t* a, const uint32_t* b) {
    asm volatile(
        "mma.sync.aligned.m16n8k16.row.col.f32.bf16.bf16.f32 "
        "{%0,%1,%2,%3}, {%4,%5,%6,%7}, {%8,%9}, {%0,%1,%2,%3};"
        : "+f"(d[0]), "+f"(d[1]), "+f"(d[2]), "+f"(d[3])
        : "r"(a[0]), "r"(a[1]), "r"(a[2]), "r"(a[3]), "r"(b[0]), "r"(b[1]));
}

// ---------------------------------------------------------------------------
// init: zero h[0] (bf16 hi/lo) + sync state  (re-run every launch -> replay safe)
// ---------------------------------------------------------------------------
__global__ void init_kernel() {
    int i = blockIdx.x * blockDim.x + threadIdx.x;
    if (i < 16384)   // 2*64*1024 bf16 = 16384 uint4
        reinterpret_cast<uint4*>(&g_hbf[0][0][0][0])[i] = make_uint4(0, 0, 0, 0);
    if (i < 8 * 32) g_wcnt[i] = 0;
    if (i == 0) g_rdone = 0;
}

// ---------------------------------------------------------------------------
// prep_x: x fp32 -> bf16 hi/lo, same [m][k] layout
// ---------------------------------------------------------------------------
__global__ void __launch_bounds__(256) prep_x(const float* __restrict__ x) {
    size_t i = (size_t)blockIdx.x * blockDim.x + threadIdx.x;
    size_t o = i * 8;
    if (o >= (size_t)B * T * I) return;
    float4 v0 = *reinterpret_cast<const float4*>(x + o);
    float4 v1 = *reinterpret_cast<const float4*>(x + o + 4);
    __nv_bfloat16 hi[8], lo[8];
    #pragma unroll
    for (int j = 0; j < 8; ++j) {
        float f = (j < 4) ? (&v0.x)[j] : (&v1.x)[j - 4];
        __nv_bfloat16 h = __float2bfloat16(f);
        hi[j] = h;
        lo[j] = __float2bfloat16(f - __bfloat162float(h));
    }
    *reinterpret_cast<uint4*>(&g_xb_hi[o]) = *reinterpret_cast<uint4*>(hi);
    *reinterpret_cast<uint4*>(&g_xb_lo[o]) = *reinterpret_cast<uint4*>(lo);
}

// ---------------------------------------------------------------------------
// prep_w: transpose Wx [k][j] -> g_wb[fused n][k] bf16 hi/lo
// ---------------------------------------------------------------------------
__global__ void __launch_bounds__(256) prep_w(
    const float* __restrict__ w0, const float* __restrict__ w1,
    const float* __restrict__ w2, const float* __restrict__ w3)
{
    __shared__ float tl[32][33];
    const int gate = blockIdx.z;
    const int jt = blockIdx.x * 32;
    const int kt = blockIdx.y * 32;
    const float* __restrict__ w = (gate == 0) ? w0 : (gate == 1) ? w1 : (gate == 2) ? w2 : w3;
    const int tx = threadIdx.x, ty = threadIdx.y;
    #pragma unroll
    for (int r = 0; r < 4; ++r)
        tl[ty + r * 8][tx] = w[(size_t)(kt + ty + r * 8) * H + jt + tx];
    __syncthreads();
    #pragma unroll
    for (int r = 0; r < 4; ++r) {
        int j = jt + ty + r * 8;
        int k = kt + tx;
        float v = tl[tx][ty + r * 8];
        __nv_bfloat16 h = __float2bfloat16(v);
        size_t fc = (size_t)gate * H + j;
        g_wb_hi[fc * I + k] = h;
        g_wb_lo[fc * I + k] = __float2bfloat16(v - __bfloat162float(h));
    }
}

// ---------------------------------------------------------------------------
// xproj via mma.sync (unchanged, 68.9% tensor)
// ---------------------------------------------------------------------------
static constexpr int XROW = 72;
static constexpr uint32_t XMAT = 128 * XROW * 2;
static constexpr size_t SMEM_MMA = 4 * XMAT;

__global__ void __launch_bounds__(256, 2) xproj_mma(
    const float* __restrict__ b0, const float* __restrict__ b1,
    const float* __restrict__ b2, const float* __restrict__ b3)
{
    extern __shared__ char sm[];
    __nv_bfloat16* sA_hi = reinterpret_cast<__nv_bfloat16*>(sm);
    __nv_bfloat16* sA_lo = reinterpret_cast<__nv_bfloat16*>(sm + XMAT);
    __nv_bfloat16* sB_hi = reinterpret_cast<__nv_bfloat16*>(sm + 2 * XMAT);
    __nv_bfloat16* sB_lo = reinterpret_cast<__nv_bfloat16*>(sm + 3 * XMAT);
    __shared__ float sbias[128];

    const int tid = threadIdx.x;
    const int wid = tid >> 5;
    const int lane = tid & 31;
    const int quad = lane >> 2;
    const int pr = lane & 3;
    const int mwarp = wid >> 2;
    const int nwarp = wid & 3;
    const int m0 = blockIdx.y * 128;
    const int n0 = blockIdx.x * 128;
    const int gate = n0 >> 10;
    const int j0f = n0 & (H - 1);
    const float* __restrict__ bias = (gate == 0) ? b0 : (gate == 1) ? b1
                                   : (gate == 2) ? b2 : b3;
    if (tid < 128) sbias[tid] = bias[j0f + tid];

    float acc[4][4][4];
    #pragma unroll
    for (int i = 0; i < 4; ++i)
        #pragma unroll
        for (int j = 0; j < 4; ++j)
            #pragma unroll
            for (int q = 0; q < 4; ++q) acc[i][j][q] = 0.0f;

    for (int c = 0; c < 16; ++c) {
        const size_t kb = (size_t)c * 64;
        #pragma unroll
        for (int i = 0; i < 4; ++i) {
            int g = tid + i * 256;
            int row = g >> 3;
            int kg = g & 7;
            size_t asrc = (size_t)(m0 + row) * I + kb + kg * 8;
            size_t bsrc = (size_t)(n0 + row) * I + kb + kg * 8;
            uint4 vah = __ldcg(reinterpret_cast<const uint4*>(&g_xb_hi[asrc]));
            uint4 val = __ldcg(reinterpret_cast<const uint4*>(&g_xb_lo[asrc]));
            uint4 vbh = __ldcg(reinterpret_cast<const uint4*>(&g_wb_hi[bsrc]));
            uint4 vbl = __ldcg(reinterpret_cast<const uint4*>(&g_wb_lo[bsrc]));
            int d = row * XROW + kg * 8;
            *reinterpret_cast<uint4*>(&sA_hi[d]) = vah;
            *reinterpret_cast<uint4*>(&sA_lo[d]) = val;
            *reinterpret_cast<uint4*>(&sB_hi[d]) = vbh;
            *reinterpret_cast<uint4*>(&sB_lo[d]) = vbl;
        }
        __syncthreads();

        #pragma unroll
        for (int kk = 0; kk < 4; ++kk) {
            const int k0 = kk * 16;
            uint32_t bh[4][2], bl[4][2];
            #pragma unroll
            for (int ns = 0; ns < 4; ++ns) {
                int nrow = nwarp * 32 + ns * 8 + quad;
                int off = nrow * XROW + k0 + pr * 2;
                bh[ns][0] = *reinterpret_cast<const uint32_t*>(&sB_hi[off]);
                bh[ns][1] = *reinterpret_cast<const uint32_t*>(&sB_hi[off + 8]);
                bl[ns][0] = *reinterpret_cast<const uint32_t*>(&sB_lo[off]);
                bl[ns][1] = *reinterpret_cast<const uint32_t*>(&sB_lo[off + 8]);
            }
            #pragma unroll
            for (int ms = 0; ms < 4; ++ms) {
                int mrow = mwarp * 64 + ms * 16 + quad;
                int o0 = mrow * XROW + k0 + pr * 2;
                int o1 = (mrow + 8) * XROW + k0 + pr * 2;
                uint32_t ah[4], al[4];
                ah[0] = *reinterpret_cast<const uint32_t*>(&sA_hi[o0]);
                ah[1] = *reinterpret_cast<const uint32_t*>(&sA_hi[o1]);
                ah[2] = *reinterpret_cast<const uint32_t*>(&sA_hi[o0 + 8]);
                ah[3] = *reinterpret_cast<const uint32_t*>(&sA_hi[o1 + 8]);
                al[0] = *reinterpret_cast<const uint32_t*>(&sA_lo[o0]);
                al[1] = *reinterpret_cast<const uint32_t*>(&sA_lo[o1]);
                al[2] = *reinterpret_cast<const uint32_t*>(&sA_lo[o0 + 8]);
                al[3] = *reinterpret_cast<const uint32_t*>(&sA_lo[o1 + 8]);
                #pragma unroll
                for (int ns = 0; ns < 4; ++ns) {
                    mma_bf16(acc[ms][ns], ah, bh[ns]);
                    mma_bf16(acc[ms][ns], ah, bl[ns]);
                    mma_bf16(acc[ms][ns], al, bh[ns]);
                }
            }
        }
        __syncthreads();
    }

    #pragma unroll
    for (int ms = 0; ms < 4; ++ms) {
        #pragma unroll
        for (int half = 0; half < 2; ++half) {
            int m = m0 + mwarp * 64 + ms * 16 + quad + half * 8;
            int t = m & (T - 1);
            int bb = m >> 9;
            size_t obase = ((size_t)t * B + bb) * G4H + n0;
            #pragma unroll
            for (int ns = 0; ns < 4; ++ns) {
                int ncol = nwarp * 32 + ns * 8 + pr * 2;
                float2 v;
                v.x = acc[ms][ns][half * 2 + 0] + sbias[ncol + 0];
                v.y = acc[ms][ns][half * 2 + 1] + sbias[ncol + 1];
                *reinterpret_cast<float2*>(&g_xproj[obase + ncol]) = v;
            }
        }
    }
}

// ---------------------------------------------------------------------------
// Persistent LSTM recurrence — R13/v4 MMA core (7.61ms-proven) with the hard
// grid barrier replaced by DATAFLOW gates:
//   - chunk c of h(t) readable when g_wcnt[c] >= 16*t (its 16 producer CTAs
//     published h(t)); polled one chunk ahead, overlapped with compute.
//   - h(t+1) writable (same buffer as h(t-1)) when g_rdone >= 128*t (all CTAs
//     finished reading h(t-1)) — one full step of slack.
// ---------------------------------------------------------------------------
static constexpr int RWS = 1032;                    // wsb row stride (halfs)
static constexpr int RHS = 136;                     // hs row stride (halfs)
static constexpr size_t WSB_HI = 0;
static constexpr size_t WSB_LO = 32 * RWS * 2;               // 66048
static constexpr size_t HS_OFF = 2 * 32 * RWS * 2;           // 132096
static constexpr size_t HS_MAT = 64 * RHS * 2;               // 17408
static constexpr size_t GT0_OFF = HS_OFF + 4 * HS_MAT;       // 201728
static constexpr int GTS = 36;
static constexpr size_t GT1_OFF = GT0_OFF + 64 * GTS * 4;
static constexpr size_t SMEM_REC = GT1_OFF + 64 * GTS * 4;   // 220160

__global__ void __launch_bounds__(512, 1) lstm_rec_mma(
    const float* __restrict__ wh0, const float* __restrict__ wh1,
    const float* __restrict__ wh2, const float* __restrict__ wh3,
    float* __restrict__ out)
{
    extern __shared__ char sm[];
    __nv_bfloat16* wsb_hi = reinterpret_cast<__nv_bfloat16*>(sm + WSB_HI);
    __nv_bfloat16* wsb_lo = reinterpret_cast<__nv_bfloat16*>(sm + WSB_LO);
    float* gt0 = reinterpret_cast<float*>(sm + GT0_OFF);
    float* gt1 = reinterpret_cast<float*>(sm + GT1_OFF);

    const int tid = threadIdx.x;
    const int cg = blockIdx.x;
    const int j0 = cg * 8;
    const int lane = tid & 31;
    const int wrp = tid >> 5;
    const int quad = lane >> 2;
    const int pr = lane & 3;
    const int nh = wrp & 1;
    const int kq = wrp >> 1;

    // ---- build resident Wh hi/lo in B-frag row layout [fc][k], once ----
    for (int idx = tid; idx < 32 * 1024; idx += 512) {
        int fc = idx & 31;
        int k = idx >> 5;
        int gate = fc >> 3, jj = fc & 7;
        const float* __restrict__ wsel = (gate == 0) ? wh0 : (gate == 1) ? wh1
                                       : (gate == 2) ? wh2 : wh3;
        float w = wsel[(size_t)k * H + j0 + jj];
        __nv_bfloat16 h = __float2bfloat16(w);
        wsb_hi[fc * RWS + k] = h;
        wsb_lo[fc * RWS + k] = __float2bfloat16(w - __bfloat162float(h));
    }
    __syncthreads();

    // pointwise ownership: one (row, jj) per thread
    const int prow = tid >> 3;
    const int pjj = tid & 7;
    float creg = 0.0f;

    // staging map
    const int srow = tid >> 4;
    const int sgrp = tid & 15;

    for (int t = 0; t < T; ++t) {
        const __nv_bfloat16* hin_hi = &g_hbf[t & 1][0][0][0];
        const __nv_bfloat16* hin_lo = &g_hbf[t & 1][1][0][0];

        // xproj prefetch for the pointwise (independent of h -> before gates)
        float xp[4];
        {
            size_t xb = ((size_t)t * B + prow) * G4H + j0 + pjj;
            #pragma unroll
            for (int g = 0; g < 4; ++g)
                xp[g] = __ldcg(&g_xproj[xb + (size_t)g * H]);
        }

        // ---- gate chunk 0 readiness, then stage chunk 0 ----
        if (tid == 0) poll_ge(&g_wcnt[0 * 32], 16u * (unsigned)t);
        __syncthreads();
        {
            char* d_hi = sm + HS_OFF;
            char* d_lo = sm + HS_OFF + HS_MAT;
            #pragma unroll
            for (int j = 0; j < 2; ++j) {
                int r = srow + j * 32;
                size_t src = (size_t)r * H + sgrp * 8;
                uint4 vh = __ldcg(reinterpret_cast<const uint4*>(hin_hi + src));
                uint4 vl = __ldcg(reinterpret_cast<const uint4*>(hin_lo + src));
                int d = (r * RHS + sgrp * 8) * 2;
                *reinterpret_cast<uint4*>(d_hi + d) = vh;
                *reinterpret_cast<uint4*>(d_lo + d) = vl;
            }
        }
        // gate chunk 1 (prefetched during iteration 0)
        if (tid == 0) poll_ge(&g_wcnt[1 * 32], 16u * (unsigned)t);
        __syncthreads();

        float acc[4][2][4];
        #pragma unroll
        for (int mt = 0; mt < 4; ++mt)
            #pragma unroll
            for (int nt = 0; nt < 2; ++nt)
                #pragma unroll
                for (int q = 0; q < 4; ++q) acc[mt][nt][q] = 0.0f;

        for (int c = 0; c < 8; ++c) {
            const int b = c & 1;
            uint4 pfh[2], pfl[2];
            if (c + 1 < 8) {
                #pragma unroll
                for (int j = 0; j < 2; ++j) {
                    int r = srow + j * 32;
                    size_t src = (size_t)r * H + (c + 1) * 128 + sgrp * 8;
                    pfh[j] = __ldcg(reinterpret_cast<const uint4*>(hin_hi + src));
                    pfl[j] = __ldcg(reinterpret_cast<const uint4*>(hin_lo + src));
                }
            }

            const __nv_bfloat16* hs_hi = reinterpret_cast<const __nv_bfloat16*>(
                sm + HS_OFF + (b * 2) * HS_MAT);
            const __nv_bfloat16* hs_lo = reinterpret_cast<const __nv_bfloat16*>(
                sm + HS_OFF + (b * 2 + 1) * HS_MAT);
            const int kglob = c * 128 + kq * 16;
            const int klocal = kq * 16;

            uint32_t Bh[2][2], Bl[2][2];
            #pragma unroll
            for (int nt = 0; nt < 2; ++nt) {
                int fr = nh * 16 + nt * 8 + quad;
                const __nv_bfloat16* ph = wsb_hi + fr * RWS + kglob + pr * 2;
                const __nv_bfloat16* pl = wsb_lo + fr * RWS + kglob + pr * 2;
                Bh[nt][0] = *reinterpret_cast<const uint32_t*>(ph);
                Bh[nt][1] = *reinterpret_cast<const uint32_t*>(ph + 8);
                Bl[nt][0] = *reinterpret_cast<const uint32_t*>(pl);
                Bl[nt][1] = *reinterpret_cast<const uint32_t*>(pl + 8);
            }
            #pragma unroll
            for (int mt = 0; mt < 4; ++mt) {
                int ar = mt * 16 + quad;
                const __nv_bfloat16* pa0 = hs_hi + ar * RHS + klocal + pr * 2;
                const __nv_bfloat16* pa1 = hs_hi + (ar + 8) * RHS + klocal + pr * 2;
                const __nv_bfloat16* pb0 = hs_lo + ar * RHS + klocal + pr * 2;
                const __nv_bfloat16* pb1 = hs_lo + (ar + 8) * RHS + klocal + pr * 2;
                uint32_t Ah[4], Al[4];
                Ah[0] = *reinterpret_cast<const uint32_t*>(pa0);
                Ah[1] = *reinterpret_cast<const uint32_t*>(pa1);
                Ah[2] = *reinterpret_cast<const uint32_t*>(pa0 + 8);
                Ah[3] = *reinterpret_cast<const uint32_t*>(pa1 + 8);
                Al[0] = *reinterpret_cast<const uint32_t*>(pb0);
                Al[1] = *reinterpret_cast<const uint32_t*>(pb1);
                Al[2] = *reinterpret_cast<const uint32_t*>(pb0 + 8);
                Al[3] = *reinterpret_cast<const uint32_t*>(pb1 + 8);
                #pragma unroll
                for (int nt = 0; nt < 2; ++nt) {
                    mma_bf16(acc[mt][nt], Ah, Bh[nt]);   // hi*hi
                    mma_bf16(acc[mt][nt], Ah, Bl[nt]);   // hi*lo
                    mma_bf16(acc[mt][nt], Al, Bh[nt]);   // lo*hi
                }
            }

            if (c + 1 < 8) {
                char* d_hi = sm + HS_OFF + (((c + 1) & 1) * 2) * HS_MAT;
                char* d_lo = d_hi + HS_MAT;
                #pragma unroll
                for (int j = 0; j < 2; ++j) {
                    int r = srow + j * 32;
                    int d = (r * RHS + sgrp * 8) * 2;
                    *reinterpret_cast<uint4*>(d_hi + d) = pfh[j];
                    *reinterpret_cast<uint4*>(d_lo + d) = pfl[j];
                }
            }
            // gate chunk c+2 (prefetched during iteration c+1), overlapped
            if (tid == 0 && c + 2 < 8)
                poll_ge(&g_wcnt[(c + 2) * 32], 16u * (unsigned)t);
            __syncthreads();
        }

        // all h(t) reads for this CTA are complete -> announce
        if (tid == 0) {
            __threadfence();
            atomicAdd(&g_rdone, 1u);
        }

        // ---- 8-way k-split reduction: pairs (2p -> gt0, 2p+1 -> gt1) ----
        #pragma unroll
        for (int p = 0; p < 4; ++p) {
            if ((kq >> 1) == p) {
                float* g = (kq & 1) ? gt1 : gt0;
                #pragma unroll
                for (int mt = 0; mt < 4; ++mt)
                    #pragma unroll
                    for (int half = 0; half < 2; ++half) {
                        int row = mt * 16 + quad + half * 8;
                        #pragma unroll
                        for (int nt = 0; nt < 2; ++nt) {
                            int col = nh * 16 + nt * 8 + pr * 2;
                            float2 v;
                            v.x = acc[mt][nt][half * 2 + 0];
                            v.y = acc[mt][nt][half * 2 + 1];
                            float* gp = g + row * GTS + col;
                            if (p == 0) {
                                *reinterpret_cast<float2*>(gp) = v;
                            } else {
                                float2 o = *reinterpret_cast<const float2*>(gp);
                                o.x += v.x; o.y += v.y;
                                *reinterpret_cast<float2*>(gp) = o;
                            }
                        }
                    }
            }
            __syncthreads();
        }

        // ---- anti-dependency gate: all CTAs finished reading h(t-1) ----
        if (tid == 0) poll_ge(&g_rdone, 128u * (unsigned)t);
        __syncthreads();

        // ---- pointwise LSTM cell ----
        {
            float gv4[4];
            #pragma unroll
            for (int g = 0; g < 4; ++g) {
                int fc = g * 8 + pjj;
                gv4[g] = gt0[prow * GTS + fc] + gt1[prow * GTS + fc] + xp[g];
            }
            float ig = fast_sigmoid(gv4[0]);
            float fg = fast_sigmoid(gv4[1]);
            float gg = fast_tanh(gv4[2]);
            float og = fast_sigmoid(gv4[3]);
            creg = fg * creg + ig * gg;
            float hv = og * fast_tanh(creg);
            int j = j0 + pjj;
            const int nb = (t + 1) & 1;
            __nv_bfloat16 hh = __float2bfloat16(hv);
            g_hbf[nb][0][prow][j] = hh;
            g_hbf[nb][1][prow][j] = __float2bfloat16(hv - __bfloat162float(hh));
            out[((size_t)prow * T + t) * H + j] = hv;
            if (t == T - 1) {
                size_t off = (size_t)B * T * H;
                out[off + (size_t)prow * H + j] = hv;
                out[off + (size_t)B * H + (size_t)prow * H + j] = creg;
            }
        }

        // ---- publish h(t+1): arrive at this CTA's chunk-group counter ----
        __syncthreads();
        if (tid == 0) {
            __threadfence();
            atomicAdd(&g_wcnt[(cg >> 4) * 32], 1u);
        }
    }
}

// ---------------------------------------------------------------------------
extern "C" void kernel_launch(void* const* d_in, const int* in_sizes, int n_in,
                              void* d_out, int out_size)
{
    const float* x   = (const float*)d_in[0];
    const float* wii = (const float*)d_in[1];
    const float* whi = (const float*)d_in[2];
    const float* bi  = (const float*)d_in[3];
    const float* wif = (const float*)d_in[4];
    const float* whf = (const float*)d_in[5];
    const float* bf  = (const float*)d_in[6];
    const float* wig = (const float*)d_in[7];
    const float* whg = (const float*)d_in[8];
    const float* bg  = (const float*)d_in[9];
    const float* wio = (const float*)d_in[10];
    const float* who = (const float*)d_in[11];
    const float* bo  = (const float*)d_in[12];
    float* out = (float*)d_out;

    cudaFuncSetAttribute(xproj_mma,
                         cudaFuncAttributeMaxDynamicSharedMemorySize,
                         (int)SMEM_MMA);
    cudaFuncSetAttribute(lstm_rec_mma,
                         cudaFuncAttributeMaxDynamicSharedMemorySize,
                         (int)SMEM_REC);

    init_kernel<<<64, 256>>>();

    // bf16 hi/lo operand prep
    prep_x<<<16384, 256>>>(x);
    {
        dim3 g(32, 32, 4), blk(32, 8);
        prep_w<<<g, blk>>>(wii, wif, wig, wio);
    }

    // tensor-core xproj
    {
        dim3 g(G4H / 128, (B * T) / 128);   // (32, 256)
        xproj_mma<<<g, 256, SMEM_MMA>>>(bi, bf, bg, bo);
    }

    // tensor-core persistent recurrence (dataflow-synced)
    lstm_rec_mma<<<NCTA, 512, SMEM_REC>>>(whi, whf, whg, who, out);
}

// round 17
// speedup vs baseline: 1.1576x; 1.1576x over previous
#include <cuda_runtime.h>
#include <cuda_bf16.h>
#include <math.h>
#include <stdint.h>

typedef unsigned long long ull;

// Problem constants
static constexpr int B = 64;
static constexpr int T = 512;
static constexpr int I = 1024;
static constexpr int H = 1024;
static constexpr int G4H = 4 * H;   // 4096

static constexpr int NCTA = 128;

// Scratch in device globals (no allocation allowed)
__device__ float g_xproj[(size_t)T * B * G4H];  // [T][B][4H]
__device__ __nv_bfloat16 g_hbf[2][2][B][H];     // [pingpong][hi/lo][row][k]
__device__ unsigned g_bar_count = 0;
__device__ unsigned g_bar_sense = 0;

// bf16 hi/lo operands for the tensor-core xproj GEMM
__device__ __nv_bfloat16 g_xb_hi[(size_t)B * T * I];   // [m][k]
__device__ __nv_bfloat16 g_xb_lo[(size_t)B * T * I];
__device__ __nv_bfloat16 g_wb_hi[(size_t)G4H * I];     // [fused n][k]  (W^T)
__device__ __nv_bfloat16 g_wb_lo[(size_t)G4H * I];

// ---------------------------------------------------------------------------
// helpers
// ---------------------------------------------------------------------------
__device__ __forceinline__ float fast_tanh(float x) {
    float y; asm("tanh.approx.f32 %0, %1;" : "=f"(y) : "f"(x)); return y;
}
__device__ __forceinline__ float fast_sigmoid(float x) {
    return 0.5f * fast_tanh(0.5f * x) + 0.5f;
}

// mma.sync m16n8k16 bf16 (baseline PTX — compiles for compute_103)
__device__ __forceinline__ void mma_bf16(float* d, const uint32_t* a, const uint32_t* b) {
    asm volatile(
        "mma.sync.aligned.m16n8k16.row.col.f32.bf16.bf16.f32 "
        "{%0,%1,%2,%3}, {%4,%5,%6,%7}, {%8,%9}, {%0,%1,%2,%3};"
        : "+f"(d[0]), "+f"(d[1]), "+f"(d[2]), "+f"(d[3])
        : "r"(a[0]), "r"(a[1]), "r"(a[2]), "r"(a[3]), "r"(b[0]), "r"(b[1]));
}

// ---------------------------------------------------------------------------
// init: zero h[0] (bf16 hi/lo) + barrier state
// ---------------------------------------------------------------------------
__global__ void init_kernel() {
    int i = blockIdx.x * blockDim.x + threadIdx.x;
    if (i < 16384)   // 2*64*1024 bf16 = 16384 uint4
        reinterpret_cast<uint4*>(&g_hbf[0][0][0][0])[i] = make_uint4(0, 0, 0, 0);
    if (i == 0) { g_bar_count = 0; g_bar_sense = 0; }
}

// ---------------------------------------------------------------------------
// prep_x: x fp32 -> bf16 hi/lo, same [m][k] layout
// ---------------------------------------------------------------------------
__global__ void __launch_bounds__(256) prep_x(const float* __restrict__ x) {
    size_t i = (size_t)blockIdx.x * blockDim.x + threadIdx.x;
    size_t o = i * 8;
    if (o >= (size_t)B * T * I) return;
    float4 v0 = *reinterpret_cast<const float4*>(x + o);
    float4 v1 = *reinterpret_cast<const float4*>(x + o + 4);
    __nv_bfloat16 hi[8], lo[8];
    #pragma unroll
    for (int j = 0; j < 8; ++j) {
        float f = (j < 4) ? (&v0.x)[j] : (&v1.x)[j - 4];
        __nv_bfloat16 h = __float2bfloat16(f);
        hi[j] = h;
        lo[j] = __float2bfloat16(f - __bfloat162float(h));
    }
    *reinterpret_cast<uint4*>(&g_xb_hi[o]) = *reinterpret_cast<uint4*>(hi);
    *reinterpret_cast<uint4*>(&g_xb_lo[o]) = *reinterpret_cast<uint4*>(lo);
}

// ---------------------------------------------------------------------------
// prep_w: transpose Wx [k][j] -> g_wb[fused n][k] bf16 hi/lo
// ---------------------------------------------------------------------------
__global__ void __launch_bounds__(256) prep_w(
    const float* __restrict__ w0, const float* __restrict__ w1,
    const float* __restrict__ w2, const float* __restrict__ w3)
{
    __shared__ float tl[32][33];
    const int gate = blockIdx.z;
    const int jt = blockIdx.x * 32;
    const int kt = blockIdx.y * 32;
    const float* __restrict__ w = (gate == 0) ? w0 : (gate == 1) ? w1 : (gate == 2) ? w2 : w3;
    const int tx = threadIdx.x, ty = threadIdx.y;
    #pragma unroll
    for (int r = 0; r < 4; ++r)
        tl[ty + r * 8][tx] = w[(size_t)(kt + ty + r * 8) * H + jt + tx];
    __syncthreads();
    #pragma unroll
    for (int r = 0; r < 4; ++r) {
        int j = jt + ty + r * 8;
        int k = kt + tx;
        float v = tl[tx][ty + r * 8];
        __nv_bfloat16 h = __float2bfloat16(v);
        size_t fc = (size_t)gate * H + j;
        g_wb_hi[fc * I + k] = h;
        g_wb_lo[fc * I + k] = __float2bfloat16(v - __bfloat162float(h));
    }
}

// ---------------------------------------------------------------------------
// xproj via mma.sync (unchanged, 68.9% tensor)
// ---------------------------------------------------------------------------
static constexpr int XROW = 72;
static constexpr uint32_t XMAT = 128 * XROW * 2;
static constexpr size_t SMEM_MMA = 4 * XMAT;

__global__ void __launch_bounds__(256, 2) xproj_mma(
    const float* __restrict__ b0, const float* __restrict__ b1,
    const float* __restrict__ b2, const float* __restrict__ b3)
{
    extern __shared__ char sm[];
    __nv_bfloat16* sA_hi = reinterpret_cast<__nv_bfloat16*>(sm);
    __nv_bfloat16* sA_lo = reinterpret_cast<__nv_bfloat16*>(sm + XMAT);
    __nv_bfloat16* sB_hi = reinterpret_cast<__nv_bfloat16*>(sm + 2 * XMAT);
    __nv_bfloat16* sB_lo = reinterpret_cast<__nv_bfloat16*>(sm + 3 * XMAT);
    __shared__ float sbias[128];

    const int tid = threadIdx.x;
    const int wid = tid >> 5;
    const int lane = tid & 31;
    const int quad = lane >> 2;
    const int pr = lane & 3;
    const int mwarp = wid >> 2;
    const int nwarp = wid & 3;
    const int m0 = blockIdx.y * 128;
    const int n0 = blockIdx.x * 128;
    const int gate = n0 >> 10;
    const int j0f = n0 & (H - 1);
    const float* __restrict__ bias = (gate == 0) ? b0 : (gate == 1) ? b1
                                   : (gate == 2) ? b2 : b3;
    if (tid < 128) sbias[tid] = bias[j0f + tid];

    float acc[4][4][4];
    #pragma unroll
    for (int i = 0; i < 4; ++i)
        #pragma unroll
        for (int j = 0; j < 4; ++j)
            #pragma unroll
            for (int q = 0; q < 4; ++q) acc[i][j][q] = 0.0f;

    for (int c = 0; c < 16; ++c) {
        const size_t kb = (size_t)c * 64;
        #pragma unroll
        for (int i = 0; i < 4; ++i) {
            int g = tid + i * 256;
            int row = g >> 3;
            int kg = g & 7;
            size_t asrc = (size_t)(m0 + row) * I + kb + kg * 8;
            size_t bsrc = (size_t)(n0 + row) * I + kb + kg * 8;
            uint4 vah = __ldcg(reinterpret_cast<const uint4*>(&g_xb_hi[asrc]));
            uint4 val = __ldcg(reinterpret_cast<const uint4*>(&g_xb_lo[asrc]));
            uint4 vbh = __ldcg(reinterpret_cast<const uint4*>(&g_wb_hi[bsrc]));
            uint4 vbl = __ldcg(reinterpret_cast<const uint4*>(&g_wb_lo[bsrc]));
            int d = row * XROW + kg * 8;
            *reinterpret_cast<uint4*>(&sA_hi[d]) = vah;
            *reinterpret_cast<uint4*>(&sA_lo[d]) = val;
            *reinterpret_cast<uint4*>(&sB_hi[d]) = vbh;
            *reinterpret_cast<uint4*>(&sB_lo[d]) = vbl;
        }
        __syncthreads();

        #pragma unroll
        for (int kk = 0; kk < 4; ++kk) {
            const int k0 = kk * 16;
            uint32_t bh[4][2], bl[4][2];
            #pragma unroll
            for (int ns = 0; ns < 4; ++ns) {
                int nrow = nwarp * 32 + ns * 8 + quad;
                int off = nrow * XROW + k0 + pr * 2;
                bh[ns][0] = *reinterpret_cast<const uint32_t*>(&sB_hi[off]);
                bh[ns][1] = *reinterpret_cast<const uint32_t*>(&sB_hi[off + 8]);
                bl[ns][0] = *reinterpret_cast<const uint32_t*>(&sB_lo[off]);
                bl[ns][1] = *reinterpret_cast<const uint32_t*>(&sB_lo[off + 8]);
            }
            #pragma unroll
            for (int ms = 0; ms < 4; ++ms) {
                int mrow = mwarp * 64 + ms * 16 + quad;
                int o0 = mrow * XROW + k0 + pr * 2;
                int o1 = (mrow + 8) * XROW + k0 + pr * 2;
                uint32_t ah[4], al[4];
                ah[0] = *reinterpret_cast<const uint32_t*>(&sA_hi[o0]);
                ah[1] = *reinterpret_cast<const uint32_t*>(&sA_hi[o1]);
                ah[2] = *reinterpret_cast<const uint32_t*>(&sA_hi[o0 + 8]);
                ah[3] = *reinterpret_cast<const uint32_t*>(&sA_hi[o1 + 8]);
                al[0] = *reinterpret_cast<const uint32_t*>(&sA_lo[o0]);
                al[1] = *reinterpret_cast<const uint32_t*>(&sA_lo[o1]);
                al[2] = *reinterpret_cast<const uint32_t*>(&sA_lo[o0 + 8]);
                al[3] = *reinterpret_cast<const uint32_t*>(&sA_lo[o1 + 8]);
                #pragma unroll
                for (int ns = 0; ns < 4; ++ns) {
                    mma_bf16(acc[ms][ns], ah, bh[ns]);
                    mma_bf16(acc[ms][ns], ah, bl[ns]);
                    mma_bf16(acc[ms][ns], al, bh[ns]);
                }
            }
        }
        __syncthreads();
    }

    #pragma unroll
    for (int ms = 0; ms < 4; ++ms) {
        #pragma unroll
        for (int half = 0; half < 2; ++half) {
            int m = m0 + mwarp * 64 + ms * 16 + quad + half * 8;
            int t = m & (T - 1);
            int bb = m >> 9;
            size_t obase = ((size_t)t * B + bb) * G4H + n0;
            #pragma unroll
            for (int ns = 0; ns < 4; ++ns) {
                int ncol = nwarp * 32 + ns * 8 + pr * 2;
                float2 v;
                v.x = acc[ms][ns][half * 2 + 0] + sbias[ncol + 0];
                v.y = acc[ms][ns][half * 2 + 1] + sbias[ncol + 1];
                *reinterpret_cast<float2*>(&g_xproj[obase + ncol]) = v;
            }
        }
    }
}

// ---------------------------------------------------------------------------
// Persistent LSTM recurrence — EXACT R13 structure (7.61ms-proven), with two
// micro-cuts only:
//  (1) barrier arrival: __threadfence + relaxed atomicAdd -> single
//      atom.acq_rel.gpu.global.add (same ordering, one membar.gl fewer)
//  (2) the redundant __syncthreads at the end of the LAST chunk iteration is
//      removed (reduction pass 0 writes gt, disjoint from hs; the pass-0
//      sync already rendezvouses all warps before pass 1 reads).
// ---------------------------------------------------------------------------
static constexpr int RWS = 1032;                    // wsb row stride (halfs)
static constexpr int RHS = 136;                     // hs row stride (halfs)
static constexpr size_t WSB_HI = 0;
static constexpr size_t WSB_LO = 32 * RWS * 2;               // 66048
static constexpr size_t HS_OFF = 2 * 32 * RWS * 2;           // 132096
static constexpr size_t HS_MAT = 64 * RHS * 2;               // 17408
static constexpr size_t GT0_OFF = HS_OFF + 4 * HS_MAT;       // 201728
static constexpr int GTS = 36;
static constexpr size_t GT1_OFF = GT0_OFF + 64 * GTS * 4;
static constexpr size_t SMEM_REC = GT1_OFF + 64 * GTS * 4;   // 220160

__global__ void __launch_bounds__(512, 1) lstm_rec_mma(
    const float* __restrict__ wh0, const float* __restrict__ wh1,
    const float* __restrict__ wh2, const float* __restrict__ wh3,
    float* __restrict__ out)
{
    extern __shared__ char sm[];
    __nv_bfloat16* wsb_hi = reinterpret_cast<__nv_bfloat16*>(sm + WSB_HI);
    __nv_bfloat16* wsb_lo = reinterpret_cast<__nv_bfloat16*>(sm + WSB_LO);
    float* gt0 = reinterpret_cast<float*>(sm + GT0_OFF);
    float* gt1 = reinterpret_cast<float*>(sm + GT1_OFF);
    __shared__ unsigned s_sense;

    const int tid = threadIdx.x;
    const int cg = blockIdx.x;
    const int j0 = cg * 8;
    const int lane = tid & 31;
    const int wrp = tid >> 5;
    const int quad = lane >> 2;
    const int pr = lane & 3;
    const int nh = wrp & 1;
    const int kq = wrp >> 1;

    // ---- build resident Wh hi/lo in B-frag row layout [fc][k], once ----
    for (int idx = tid; idx < 32 * 1024; idx += 512) {
        int fc = idx & 31;
        int k = idx >> 5;
        int gate = fc >> 3, jj = fc & 7;
        const float* __restrict__ wsel = (gate == 0) ? wh0 : (gate == 1) ? wh1
                                       : (gate == 2) ? wh2 : wh3;
        float w = wsel[(size_t)k * H + j0 + jj];
        __nv_bfloat16 h = __float2bfloat16(w);
        wsb_hi[fc * RWS + k] = h;
        wsb_lo[fc * RWS + k] = __float2bfloat16(w - __bfloat162float(h));
    }
    if (tid == 0) s_sense = 0;
    __syncthreads();

    // pointwise ownership: one (row, jj) per thread
    const int prow = tid >> 3;
    const int pjj = tid & 7;
    float creg = 0.0f;

    // staging map
    const int srow = tid >> 4;
    const int sgrp = tid & 15;

    for (int t = 0; t < T; ++t) {
        const __nv_bfloat16* hin_hi = &g_hbf[t & 1][0][0][0];
        const __nv_bfloat16* hin_lo = &g_hbf[t & 1][1][0][0];

        // xproj prefetch for the pointwise
        float xp[4];
        {
            size_t xb = ((size_t)t * B + prow) * G4H + j0 + pjj;
            #pragma unroll
            for (int g = 0; g < 4; ++g)
                xp[g] = __ldcg(&g_xproj[xb + (size_t)g * H]);
        }

        // stage chunk 0
        {
            char* d_hi = sm + HS_OFF;
            char* d_lo = sm + HS_OFF + HS_MAT;
            #pragma unroll
            for (int j = 0; j < 2; ++j) {
                int r = srow + j * 32;
                size_t src = (size_t)r * H + sgrp * 8;
                uint4 vh = __ldcg(reinterpret_cast<const uint4*>(hin_hi + src));
                uint4 vl = __ldcg(reinterpret_cast<const uint4*>(hin_lo + src));
                int d = (r * RHS + sgrp * 8) * 2;
                *reinterpret_cast<uint4*>(d_hi + d) = vh;
                *reinterpret_cast<uint4*>(d_lo + d) = vl;
            }
        }
        __syncthreads();

        float acc[4][2][4];
        #pragma unroll
        for (int mt = 0; mt < 4; ++mt)
            #pragma unroll
            for (int nt = 0; nt < 2; ++nt)
                #pragma unroll
                for (int q = 0; q < 4; ++q) acc[mt][nt][q] = 0.0f;

        for (int c = 0; c < 8; ++c) {
            const int b = c & 1;
            uint4 pfh[2], pfl[2];
            if (c + 1 < 8) {
                #pragma unroll
                for (int j = 0; j < 2; ++j) {
                    int r = srow + j * 32;
                    size_t src = (size_t)r * H + (c + 1) * 128 + sgrp * 8;
                    pfh[j] = __ldcg(reinterpret_cast<const uint4*>(hin_hi + src));
                    pfl[j] = __ldcg(reinterpret_cast<const uint4*>(hin_lo + src));
                }
            }

            const __nv_bfloat16* hs_hi = reinterpret_cast<const __nv_bfloat16*>(
                sm + HS_OFF + (b * 2) * HS_MAT);
            const __nv_bfloat16* hs_lo = reinterpret_cast<const __nv_bfloat16*>(
                sm + HS_OFF + (b * 2 + 1) * HS_MAT);
            const int kglob = c * 128 + kq * 16;
            const int klocal = kq * 16;

            uint32_t Bh[2][2], Bl[2][2];
            #pragma unroll
            for (int nt = 0; nt < 2; ++nt) {
                int fr = nh * 16 + nt * 8 + quad;
                const __nv_bfloat16* ph = wsb_hi + fr * RWS + kglob + pr * 2;
                const __nv_bfloat16* pl = wsb_lo + fr * RWS + kglob + pr * 2;
                Bh[nt][0] = *reinterpret_cast<const uint32_t*>(ph);
                Bh[nt][1] = *reinterpret_cast<const uint32_t*>(ph + 8);
                Bl[nt][0] = *reinterpret_cast<const uint32_t*>(pl);
                Bl[nt][1] = *reinterpret_cast<const uint32_t*>(pl + 8);
            }
            #pragma unroll
            for (int mt = 0; mt < 4; ++mt) {
                int ar = mt * 16 + quad;
                const __nv_bfloat16* pa0 = hs_hi + ar * RHS + klocal + pr * 2;
                const __nv_bfloat16* pa1 = hs_hi + (ar + 8) * RHS + klocal + pr * 2;
                const __nv_bfloat16* pb0 = hs_lo + ar * RHS + klocal + pr * 2;
                const __nv_bfloat16* pb1 = hs_lo + (ar + 8) * RHS + klocal + pr * 2;
                uint32_t Ah[4], Al[4];
                Ah[0] = *reinterpret_cast<const uint32_t*>(pa0);
                Ah[1] = *reinterpret_cast<const uint32_t*>(pa1);
                Ah[2] = *reinterpret_cast<const uint32_t*>(pa0 + 8);
                Ah[3] = *reinterpret_cast<const uint32_t*>(pa1 + 8);
                Al[0] = *reinterpret_cast<const uint32_t*>(pb0);
                Al[1] = *reinterpret_cast<const uint32_t*>(pb1);
                Al[2] = *reinterpret_cast<const uint32_t*>(pb0 + 8);
                Al[3] = *reinterpret_cast<const uint32_t*>(pb1 + 8);
                #pragma unroll
                for (int nt = 0; nt < 2; ++nt) {
                    mma_bf16(acc[mt][nt], Ah, Bh[nt]);   // hi*hi
                    mma_bf16(acc[mt][nt], Ah, Bl[nt]);   // hi*lo
                    mma_bf16(acc[mt][nt], Al, Bh[nt]);   // lo*hi
                }
            }

            if (c + 1 < 8) {
                char* d_hi = sm + HS_OFF + (((c + 1) & 1) * 2) * HS_MAT;
                char* d_lo = d_hi + HS_MAT;
                #pragma unroll
                for (int j = 0; j < 2; ++j) {
                    int r = srow + j * 32;
                    int d = (r * RHS + sgrp * 8) * 2;
                    *reinterpret_cast<uint4*>(d_hi + d) = pfh[j];
                    *reinterpret_cast<uint4*>(d_lo + d) = pfl[j];
                }
                __syncthreads();     // (2) last-iteration sync removed
            }
        }

        // ---- 8-way k-split reduction: pairs (2p -> gt0, 2p+1 -> gt1) ----
        #pragma unroll
        for (int p = 0; p < 4; ++p) {
            if ((kq >> 1) == p) {
                float* g = (kq & 1) ? gt1 : gt0;
                #pragma unroll
                for (int mt = 0; mt < 4; ++mt)
                    #pragma unroll
                    for (int half = 0; half < 2; ++half) {
                        int row = mt * 16 + quad + half * 8;
                        #pragma unroll
                        for (int nt = 0; nt < 2; ++nt) {
                            int col = nh * 16 + nt * 8 + pr * 2;
                            float2 v;
                            v.x = acc[mt][nt][half * 2 + 0];
                            v.y = acc[mt][nt][half * 2 + 1];
                            float* gp = g + row * GTS + col;
                            if (p == 0) {
                                *reinterpret_cast<float2*>(gp) = v;
                            } else {
                                float2 o = *reinterpret_cast<const float2*>(gp);
                                o.x += v.x; o.y += v.y;
                                *reinterpret_cast<float2*>(gp) = o;
                            }
                        }
                    }
            }
            __syncthreads();
        }

        // ---- pointwise LSTM cell ----
        {
            float gv4[4];
            #pragma unroll
            for (int g = 0; g < 4; ++g) {
                int fc = g * 8 + pjj;
                gv4[g] = gt0[prow * GTS + fc] + gt1[prow * GTS + fc] + xp[g];
            }
            float ig = fast_sigmoid(gv4[0]);
            float fg = fast_sigmoid(gv4[1]);
            float gg = fast_tanh(gv4[2]);
            float og = fast_sigmoid(gv4[3]);
            creg = fg * creg + ig * gg;
            float hv = og * fast_tanh(creg);
            int j = j0 + pjj;
            const int nb = (t + 1) & 1;
            __nv_bfloat16 hh = __float2bfloat16(hv);
            g_hbf[nb][0][prow][j] = hh;
            g_hbf[nb][1][prow][j] = __float2bfloat16(hv - __bfloat162float(hh));
            out[((size_t)prow * T + t) * H + j] = hv;
            if (t == T - 1) {
                size_t off = (size_t)B * T * H;
                out[off + (size_t)prow * H + j] = hv;
                out[off + (size_t)B * H + (size_t)prow * H + j] = creg;
            }
        }

        // ---- grid barrier (central atomic, R13-proven; acq_rel arrival) ----
        __syncthreads();
        if (tid == 0) {
            unsigned s = s_sense ^ 1u;
            s_sense = s;
            unsigned old;
            asm volatile("atom.acq_rel.gpu.global.add.u32 %0, [%1], %2;"
                         : "=r"(old) : "l"(&g_bar_count), "r"(1u) : "memory");
            if (old == NCTA - 1u) {
                asm volatile("st.relaxed.gpu.global.u32 [%0], %1;"
                             :: "l"(&g_bar_count), "r"(0u) : "memory");
                asm volatile("st.release.gpu.global.u32 [%0], %1;"
                             :: "l"(&g_bar_sense), "r"(s) : "memory");
            } else {
                unsigned v;
                while (true) {
                    asm volatile("ld.acquire.gpu.global.u32 %0, [%1];"
                                 : "=r"(v) : "l"(&g_bar_sense) : "memory");
                    if (v == s) break;
                    __nanosleep(32);
                }
            }
        }
        __syncthreads();
    }
}

// ---------------------------------------------------------------------------
extern "C" void kernel_launch(void* const* d_in, const int* in_sizes, int n_in,
                              void* d_out, int out_size)
{
    const float* x   = (const float*)d_in[0];
    const float* wii = (const float*)d_in[1];
    const float* whi = (const float*)d_in[2];
    const float* bi  = (const float*)d_in[3];
    const float* wif = (const float*)d_in[4];
    const float* whf = (const float*)d_in[5];
    const float* bf  = (const float*)d_in[6];
    const float* wig = (const float*)d_in[7];
    const float* whg = (const float*)d_in[8];
    const float* bg  = (const float*)d_in[9];
    const float* wio = (const float*)d_in[10];
    const float* who = (const float*)d_in[11];
    const float* bo  = (const float*)d_in[12];
    float* out = (float*)d_out;

    cudaFuncSetAttribute(xproj_mma,
                         cudaFuncAttributeMaxDynamicSharedMemorySize,
                         (int)SMEM_MMA);
    cudaFuncSetAttribute(lstm_rec_mma,
                         cudaFuncAttributeMaxDynamicSharedMemorySize,
                         (int)SMEM_REC);

    init_kernel<<<64, 256>>>();

    // bf16 hi/lo operand prep
    prep_x<<<16384, 256>>>(x);
    {
        dim3 g(32, 32, 4), blk(32, 8);
        prep_w<<<g, blk>>>(wii, wif, wig, wio);
    }

    // tensor-core xproj
    {
        dim3 g(G4H / 128, (B * T) / 128);   // (32, 256)
        xproj_mma<<<g, 256, SMEM_MMA>>>(bi, bf, bg, bo);
    }

    // tensor-core persistent recurrence
    lstm_rec_mma<<<NCTA, 512, SMEM_REC>>>(whi, whf, whg, who, out);
}